// round 13
// baseline (speedup 1.0000x reference)
#include <cuda_runtime.h>
#include <cuda_bf16.h>
#include <cstddef>

// Problem constants
#define B_   8
#define HW_  3136          // 56*56
#define NPIX (B_*HW_)      // 25088
#define C1   256
#define MID  64
#define RED  16
#define GRP  4
#define GC_  16
#define KK   49            // 7*7
#define GKK  196           // 4*49

#define NB_GEMM 392        // 49*8 pixel-tile blocks for gemm
#define NB_WR   98         // NPIX/256
#define NB_INV  112        // 14*8 per channel-group

// ---------------- scratch (device globals; no allocation allowed) ----------------
__device__ float g_buf1[B_ * MID * HW_];   // conv1 raw output
__device__ float g_t   [B_ * RED * HW_];   // reduce conv raw output
__device__ float g_inv [B_ * MID * HW_];   // involution raw output
__device__ float g_y3  [B_ * C1  * HW_];   // conv3 raw output
__device__ float g_ps1[MID * NB_GEMM], g_pq1[MID * NB_GEMM];
__device__ float g_pst[RED * NB_WR],   g_pqt[RED * NB_WR];
__device__ float g_ps2[MID * NB_INV],  g_pq2[MID * NB_INV];
__device__ float g_ps3[C1  * NB_GEMM], g_pq3[C1  * NB_GEMM];
__device__ float g_sc1[MID],  g_sh1[MID];
__device__ float g_sc2[MID],  g_sh2[MID];

// ---------------- finalize: combine per-block partials into scale/shift ----------
__global__ void finalize_kernel(const float* __restrict__ ps, const float* __restrict__ pq,
                                int n, const float* __restrict__ gam, const float* __restrict__ bet,
                                float* __restrict__ scale, float* __restrict__ shift)
{
    const int c = blockIdx.x;
    const int tid = threadIdx.x;
    float s = 0.f, q = 0.f;
    for (int i = tid; i < n; i += 256) { s += ps[c * n + i]; q += pq[c * n + i]; }
    __shared__ float sh_s[256], sh_q[256];
    sh_s[tid] = s; sh_q[tid] = q;
    __syncthreads();
    for (int off = 128; off > 0; off >>= 1) {
        if (tid < off) { sh_s[tid] += sh_s[tid + off]; sh_q[tid] += sh_q[tid + off]; }
        __syncthreads();
    }
    if (tid == 0) {
        const float nn = (float)NPIX;
        float m = sh_s[0] / nn;
        float v = sh_q[0] / nn - m * m;
        float inv = rsqrtf(v + 1e-5f);
        float sc = gam[c] * inv;
        scale[c] = sc;
        shift[c] = bet[c] - m * sc;
    }
}

// ---------------- tiled GEMM + fused per-channel partial stats -------------------
// (known-good geometry) 64x64 output tile, 256 threads, 4x4 micro, KC=32.
template<int KDIM, bool AFF>
__global__ void __launch_bounds__(256)
gemm64_kernel(const float* __restrict__ in, const float* __restrict__ W,
              float* __restrict__ out, int Mtot,
              const float* __restrict__ scale, const float* __restrict__ shift,
              float* __restrict__ ps, float* __restrict__ pq)
{
    const int bx    = blockIdx.x;
    const int b     = bx / 49;
    const int ntile = bx % 49;
    const int hw0   = ntile * 64;
    const int m0    = blockIdx.y * 64;
    const int tid   = threadIdx.x;
    const int tx    = tid & 15;
    const int ty    = tid >> 4;

    __shared__ float sW[64][32];
    __shared__ float sX[32][64];

    const float* inb = in + (size_t)b * KDIM * HW_ + hw0;

    float acc[4][4];
#pragma unroll
    for (int i = 0; i < 4; i++)
#pragma unroll
        for (int j = 0; j < 4; j++) acc[i][j] = 0.f;

    for (int c0 = 0; c0 < KDIM; c0 += 32) {
#pragma unroll
        for (int r = 0; r < 2; r++) {
            int f = tid + r * 256;
            int m = f >> 3;
            int ks = f & 7;
            float4 wv = *reinterpret_cast<const float4*>(W + (size_t)(m0 + m) * KDIM + c0 + ks * 4);
            *reinterpret_cast<float4*>(&sW[m][ks * 4]) = wv;
        }
#pragma unroll
        for (int r = 0; r < 2; r++) {
            int f = tid + r * 256;
            int kk = f >> 4;
            int ns = f & 15;
            float4 xv = *reinterpret_cast<const float4*>(inb + (size_t)(c0 + kk) * HW_ + ns * 4);
            if (AFF) {
                float s = scale[c0 + kk], sh = shift[c0 + kk];
                xv.x = fmaxf(xv.x * s + sh, 0.f);
                xv.y = fmaxf(xv.y * s + sh, 0.f);
                xv.z = fmaxf(xv.z * s + sh, 0.f);
                xv.w = fmaxf(xv.w * s + sh, 0.f);
            }
            *reinterpret_cast<float4*>(&sX[kk][ns * 4]) = xv;
        }
        __syncthreads();
#pragma unroll
        for (int kk = 0; kk < 32; kk++) {
            float4 xv = *reinterpret_cast<const float4*>(&sX[kk][tx * 4]);
#pragma unroll
            for (int i = 0; i < 4; i++) {
                float wv = sW[ty + 16 * i][kk];
                acc[i][0] += wv * xv.x;
                acc[i][1] += wv * xv.y;
                acc[i][2] += wv * xv.z;
                acc[i][3] += wv * xv.w;
            }
        }
        __syncthreads();
    }
    float* outb = out + ((size_t)b * Mtot + m0) * HW_ + hw0;
#pragma unroll
    for (int i = 0; i < 4; i++) {
        float4 v = make_float4(acc[i][0], acc[i][1], acc[i][2], acc[i][3]);
        *reinterpret_cast<float4*>(outb + (size_t)(ty + 16 * i) * HW_ + tx * 4) = v;
    }

    // fused per-channel partial (sum, sumsq) over this block's 64 pixels
#pragma unroll
    for (int i = 0; i < 4; i++) {
        float s = acc[i][0] + acc[i][1] + acc[i][2] + acc[i][3];
        float q = acc[i][0] * acc[i][0] + acc[i][1] * acc[i][1]
                + acc[i][2] * acc[i][2] + acc[i][3] * acc[i][3];
#pragma unroll
        for (int off = 8; off > 0; off >>= 1) {
            s += __shfl_down_sync(0xffffffffu, s, off, 16);
            q += __shfl_down_sync(0xffffffffu, q, off, 16);
        }
        if (tx == 0) {
            int ch = m0 + ty + 16 * i;
            ps[(size_t)ch * NB_GEMM + bx] = s;
            pq[(size_t)ch * NB_GEMM + bx] = q;
        }
    }
}

// ---------------- reduce conv (M=16, K=64) + fused partial stats -----------------
__global__ void __launch_bounds__(256)
conv_wr_kernel(const float* __restrict__ in, const float* __restrict__ wr,
               const float* __restrict__ scale, const float* __restrict__ shift,
               float* __restrict__ out, float* __restrict__ ps, float* __restrict__ pq)
{
    __shared__ float swT[64][16];   // transposed weights [c][m]
    __shared__ float ssc[64], ssh[64];
    const int tid = threadIdx.x;
    for (int e = tid; e < 16 * 64; e += 256) { int m = e >> 6, c = e & 63; swT[c][m] = wr[e]; }
    if (tid < 64) { ssc[tid] = scale[tid]; ssh[tid] = shift[tid]; }
    __syncthreads();

    const int p  = blockIdx.x * 256 + tid;
    const int b  = p / HW_, hw = p % HW_;
    const float* pin = in + (size_t)b * MID * HW_ + hw;

    float acc[16];
#pragma unroll
    for (int m = 0; m < 16; m++) acc[m] = 0.f;

#pragma unroll 4
    for (int c = 0; c < 64; c++) {
        float v = fmaxf(pin[(size_t)c * HW_] * ssc[c] + ssh[c], 0.f);
        const float4* w4 = reinterpret_cast<const float4*>(swT[c]);
#pragma unroll
        for (int q = 0; q < 4; q++) {
            float4 w = w4[q];
            acc[4 * q + 0] += w.x * v;
            acc[4 * q + 1] += w.y * v;
            acc[4 * q + 2] += w.z * v;
            acc[4 * q + 3] += w.w * v;
        }
    }
    float* pout = out + (size_t)b * RED * HW_ + hw;
#pragma unroll
    for (int m = 0; m < 16; m++) pout[(size_t)m * HW_] = acc[m];

    const int wid = tid >> 5, lane = tid & 31;
    __shared__ float wsum[8][16], wq[8][16];
#pragma unroll
    for (int m = 0; m < 16; m++) {
        float s = acc[m], q = acc[m] * acc[m];
#pragma unroll
        for (int off = 16; off > 0; off >>= 1) {
            s += __shfl_down_sync(0xffffffffu, s, off);
            q += __shfl_down_sync(0xffffffffu, q, off);
        }
        if (lane == 0) { wsum[wid][m] = s; wq[wid][m] = q; }
    }
    __syncthreads();
    if (tid < 16) {
        float s = 0.f, q = 0.f;
#pragma unroll
        for (int w = 0; w < 8; w++) { s += wsum[w][tid]; q += wq[w][tid]; }
        ps[tid * NB_WR + blockIdx.x] = s;
        pq[tid * NB_WR + blockIdx.x] = q;
    }
}

// ---------------- fused involution v2: 448 threads, split kernel-gen & channels --
// grid (14 row-tiles, 4 groups, 8 batch); block 448 = 2 halves x 224 pixels.
// Stage A: halves cooperatively compute wk[49] per pixel -> s_w (smem).
// Stage B: each thread MACs 8 channels (half*8..) for its pixel.
__global__ void __launch_bounds__(448)
involution_kernel(const float* __restrict__ buf1, const float* __restrict__ tin,
                  const float* __restrict__ ws,
                  const float* __restrict__ pst, const float* __restrict__ pqt,
                  const float* __restrict__ gr, const float* __restrict__ br,
                  const float* __restrict__ scale, const float* __restrict__ shift,
                  float* __restrict__ out, float* __restrict__ ps, float* __restrict__ pq)
{
    extern __shared__ float smem[];
    float* s_z  = smem;                     // [16][10][62] = 9920
    float* s_t  = smem + 9920;              // [16][224]    = 3584
    float* s_sw = smem + 13504;             // [49][16]     = 784
    float* s_w  = smem + 14288;             // [49][224]    = 10976
    float* s_tc = smem + 25264;             // [16]
    float* s_th = smem + 25280;             // [16]  (total 25296 floats)

    const int rt = blockIdx.x, g = blockIdx.y, b = blockIdx.z;
    const int r0 = rt * 4;
    const int tid  = threadIdx.x;
    const int pix  = tid % 224;
    const int half = tid / 224;

    // ws rows for this group: [49][16]
    for (int e = tid; e < KK * RED; e += 448) s_sw[e] = ws[(size_t)g * KK * RED + e];

    // fused BNt finalize: 16 channels, 8 lanes each (threads 0..127)
    if (tid < 128) {
        int ch = tid >> 3, part = tid & 7;
        float s = 0.f, q = 0.f;
        for (int i = part; i < NB_WR; i += 8) {
            s += pst[ch * NB_WR + i];
            q += pqt[ch * NB_WR + i];
        }
#pragma unroll
        for (int off = 4; off > 0; off >>= 1) {
            s += __shfl_down_sync(0xffffffffu, s, off, 8);
            q += __shfl_down_sync(0xffffffffu, q, off, 8);
        }
        if (part == 0) {
            const float nn = (float)NPIX;
            float m = s / nn;
            float v = q / nn - m * m;
            float sc = gr[ch] * rsqrtf(v + 1e-5f);
            s_tc[ch] = sc;
            s_th[ch] = br[ch] - m * sc;
        }
    }

    // raw t tile: [16][224]
    {
        const float* src = tin + (size_t)b * RED * HW_ + r0 * 56;
        for (int e = tid; e < 16 * 224; e += 448)
            s_t[e] = src[(size_t)(e / 224) * HW_ + (e % 224)];
    }

    // z1 tile with halo, BN1 affine + ReLU applied on load
    {
        const float* src = buf1 + ((size_t)b * MID + g * GC_) * HW_;
        for (int e = tid; e < 16 * 10 * 62; e += 448) {
            int c   = e / 620;
            int rem = e - c * 620;
            int ry  = rem / 62;
            int cx  = rem - ry * 62;
            int gy  = r0 - 3 + ry;
            int gx  = cx - 3;
            float v = 0.f;
            if (gy >= 0 && gy < 56 && gx >= 0 && gx < 56) {
                int ch = g * GC_ + c;
                v = fmaxf(src[(size_t)c * HW_ + gy * 56 + gx] * scale[ch] + shift[ch], 0.f);
            }
            s_z[e] = v;
        }
    }
    __syncthreads();

    // Stage A: per-pixel kernels. half 0 -> taps [0,25), half 1 -> taps [25,49).
    {
        float t[16];
#pragma unroll
        for (int c = 0; c < 16; c++)
            t[c] = fmaxf(s_t[c * 224 + pix] * s_tc[c] + s_th[c], 0.f);

        const int k0 = half ? 25 : 0;
        const int k1 = half ? 49 : 25;
        for (int k = k0; k < k1; k++) {
            const float* swk = &s_sw[k * 16];
            float wk = 0.f;
#pragma unroll
            for (int c = 0; c < 16; c++) wk += swk[c] * t[c];
            s_w[k * 224 + pix] = wk;
        }
    }
    __syncthreads();

    // Stage B: MAC over 49 taps for 8 channels
    const int row = pix / 56, col = pix % 56;
    const int c0  = half * 8;
    float acc[8];
#pragma unroll
    for (int c = 0; c < 8; c++) acc[c] = 0.f;

#pragma unroll 7
    for (int k = 0; k < 49; k++) {
        float wk = s_w[k * 224 + pix];
        int dy = k / 7, dx = k - dy * 7;
        const float* zp = s_z + c0 * 620 + (row + dy) * 62 + (col + dx);
#pragma unroll
        for (int c = 0; c < 8; c++) acc[c] += wk * zp[c * 620];
    }

    float* dst = out + ((size_t)b * MID + g * GC_ + c0) * HW_ + r0 * 56 + pix;
#pragma unroll
    for (int c = 0; c < 8; c++) dst[(size_t)c * HW_] = acc[c];

    // fused BN2 partial stats: 14 warps; warps 0-6 hold channels [0,8), 7-13 hold [8,16)
    const int wid = tid >> 5, lane = tid & 31;
    __shared__ float wsum[14][8], wqq[14][8];
#pragma unroll
    for (int c = 0; c < 8; c++) {
        float s = acc[c], q = acc[c] * acc[c];
#pragma unroll
        for (int off = 16; off > 0; off >>= 1) {
            s += __shfl_down_sync(0xffffffffu, s, off);
            q += __shfl_down_sync(0xffffffffu, q, off);
        }
        if (lane == 0) { wsum[wid][c] = s; wqq[wid][c] = q; }
    }
    __syncthreads();
    if (tid < 16) {
        int hc = tid >> 3;          // which half owns this channel
        int cc = tid & 7;
        float s = 0.f, q = 0.f;
#pragma unroll
        for (int w = 0; w < 7; w++) { s += wsum[hc * 7 + w][cc]; q += wqq[hc * 7 + w][cc]; }
        int ch = g * GC_ + tid;
        int slot = b * 14 + rt;
        ps[(size_t)ch * NB_INV + slot] = s;
        pq[(size_t)ch * NB_INV + slot] = q;
    }
}

// ---------------- epilogue: relu(bn(y3) + x), fused BN3 finalize ------------------
__global__ void __launch_bounds__(256)
final_kernel(const float4* __restrict__ y3, const float4* __restrict__ xin,
             const float* __restrict__ ps, const float* __restrict__ pq,
             const float* __restrict__ g3, const float* __restrict__ b3,
             float4* __restrict__ out)
{
    const int bc = blockIdx.x;          // b*256 + c
    const int c  = bc & 255;
    const int tid = threadIdx.x;

    __shared__ float sh_s[256], sh_q[256];
    __shared__ float s_sc, s_sh;
    {
        float s = 0.f, q = 0.f;
        for (int i = tid; i < NB_GEMM; i += 256) {
            s += ps[(size_t)c * NB_GEMM + i];
            q += pq[(size_t)c * NB_GEMM + i];
        }
        sh_s[tid] = s; sh_q[tid] = q;
        __syncthreads();
        for (int off = 128; off > 0; off >>= 1) {
            if (tid < off) { sh_s[tid] += sh_s[tid + off]; sh_q[tid] += sh_q[tid + off]; }
            __syncthreads();
        }
        if (tid == 0) {
            const float nn = (float)NPIX;
            float m = sh_s[0] / nn;
            float v = sh_q[0] / nn - m * m;
            float sc = g3[c] * rsqrtf(v + 1e-5f);
            s_sc = sc;
            s_sh = b3[c] - m * sc;
        }
        __syncthreads();
    }
    const float s = s_sc, sh = s_sh;
    const size_t base = (size_t)bc * 784;      // 784 float4 per (b,c)
    for (int j = tid; j < 784; j += 256) {
        float4 a = y3[base + j], r0 = xin[base + j], r;
        r.x = fmaxf(a.x * s + sh + r0.x, 0.f);
        r.y = fmaxf(a.y * s + sh + r0.y, 0.f);
        r.z = fmaxf(a.z * s + sh + r0.z, 0.f);
        r.w = fmaxf(a.w * s + sh + r0.w, 0.f);
        out[base + j] = r;
    }
}

// ---------------- launch ---------------------------------------------------------
static void* sym_addr(const void* s) { void* p = nullptr; cudaGetSymbolAddress(&p, s); return p; }

extern "C" void kernel_launch(void* const* d_in, const int* in_sizes, int n_in,
                              void* d_out, int out_size)
{
    const float* x  = (const float*)d_in[0];
    const float* w1 = (const float*)d_in[1];
    const float* g1 = (const float*)d_in[2];
    const float* b1 = (const float*)d_in[3];
    const float* wr = (const float*)d_in[4];
    const float* gr = (const float*)d_in[5];
    const float* br = (const float*)d_in[6];
    const float* ws = (const float*)d_in[7];
    const float* g2 = (const float*)d_in[8];
    const float* b2 = (const float*)d_in[9];
    const float* w3 = (const float*)d_in[10];
    const float* g3 = (const float*)d_in[11];
    const float* b3 = (const float*)d_in[12];
    float* out = (float*)d_out;

    float* buf1 = (float*)sym_addr(g_buf1);
    float* tbuf = (float*)sym_addr(g_t);
    float* invb = (float*)sym_addr(g_inv);
    float* y3   = (float*)sym_addr(g_y3);
    float* ps1 = (float*)sym_addr(g_ps1);  float* pq1 = (float*)sym_addr(g_pq1);
    float* pst = (float*)sym_addr(g_pst);  float* pqt = (float*)sym_addr(g_pqt);
    float* ps2 = (float*)sym_addr(g_ps2);  float* pq2 = (float*)sym_addr(g_pq2);
    float* ps3 = (float*)sym_addr(g_ps3);  float* pq3 = (float*)sym_addr(g_pq3);
    float* sc1 = (float*)sym_addr(g_sc1);  float* sh1 = (float*)sym_addr(g_sh1);
    float* sc2 = (float*)sym_addr(g_sc2);  float* sh2 = (float*)sym_addr(g_sh2);

    // smem: 9920 (z) + 3584 (t) + 784 (ws) + 10976 (wk) + 32 (bn_t) floats = 101184 bytes
    const int inv_smem = (9920 + 3584 + 784 + 10976 + 32) * 4;
    cudaFuncSetAttribute(involution_kernel, cudaFuncAttributeMaxDynamicSharedMemorySize, inv_smem);

    // 1) conv1: [8,256,HW] -> buf1 [8,64,HW] (+BN1 partials)
    gemm64_kernel<256, false><<<dim3(NB_GEMM, 1), 256>>>(x, w1, buf1, MID, nullptr, nullptr, ps1, pq1);
    // 2) BN1 finalize (dual consumer: conv_wr + involution)
    finalize_kernel<<<MID, 256>>>(ps1, pq1, NB_GEMM, g1, b1, sc1, sh1);
    // 3) reduce conv: relu(bn(buf1)) -> t (+BNt partials)
    conv_wr_kernel<<<NB_WR, 256>>>(buf1, wr, sc1, sh1, tbuf, pst, pqt);
    // 4) fused involution v2 (split kernel-gen + split channels) -> inv (+BN2 partials)
    involution_kernel<<<dim3(14, GRP, B_), 448, inv_smem>>>(buf1, tbuf, ws, pst, pqt, gr, br,
                                                            sc1, sh1, invb, ps2, pq2);
    // 5) BN2 finalize
    finalize_kernel<<<MID, 256>>>(ps2, pq2, NB_INV, g2, b2, sc2, sh2);
    // 6) conv3: relu(bn(inv)) -> y3 [8,256,HW] (+BN3 partials)
    gemm64_kernel<64, true><<<dim3(NB_GEMM, 4), 256>>>(invb, w3, y3, C1, sc2, sh2, ps3, pq3);
    // 7) epilogue (fused BN3 finalize): relu(bn(y3) + x)
    final_kernel<<<B_ * C1, 256>>>((const float4*)y3, (const float4*)x, ps3, pq3, g3, b3, (float4*)out);
}

// round 14
// speedup vs baseline: 1.0893x; 1.0893x over previous
#include <cuda_runtime.h>
#include <cuda_bf16.h>
#include <cstddef>

// Problem constants
#define B_   8
#define HW_  3136          // 56*56
#define NPIX (B_*HW_)      // 25088
#define C1   256
#define MID  64
#define RED  16
#define GRP  4
#define GC_  16
#define KK   49            // 7*7
#define GKK  196           // 4*49

#define NB_GEMM 392        // 49*8 pixel-tile blocks for gemm
#define NB_WR   98         // NPIX/256
#define NB_INV  112        // 14*8 per channel-group

// ---------------- scratch (device globals; no allocation allowed) ----------------
__device__ float g_buf1[B_ * MID * HW_];   // conv1 raw output
__device__ float g_t   [B_ * RED * HW_];   // reduce conv raw output
__device__ float g_inv [B_ * MID * HW_];   // involution raw output
__device__ float g_y3  [B_ * C1  * HW_];   // conv3 raw output
__device__ float g_ps1[MID * NB_GEMM], g_pq1[MID * NB_GEMM];
__device__ float g_pst[RED * NB_WR],   g_pqt[RED * NB_WR];
__device__ float g_ps2[MID * NB_INV],  g_pq2[MID * NB_INV];
__device__ float g_ps3[C1  * NB_GEMM], g_pq3[C1  * NB_GEMM];
__device__ float g_sc1[MID],  g_sh1[MID];
__device__ float g_sc2[MID],  g_sh2[MID];

// ---------------- finalize: combine per-block partials into scale/shift ----------
__global__ void finalize_kernel(const float* __restrict__ ps, const float* __restrict__ pq,
                                int n, const float* __restrict__ gam, const float* __restrict__ bet,
                                float* __restrict__ scale, float* __restrict__ shift)
{
    const int c = blockIdx.x;
    const int tid = threadIdx.x;
    float s = 0.f, q = 0.f;
    for (int i = tid; i < n; i += 256) { s += ps[c * n + i]; q += pq[c * n + i]; }
    __shared__ float sh_s[256], sh_q[256];
    sh_s[tid] = s; sh_q[tid] = q;
    __syncthreads();
    for (int off = 128; off > 0; off >>= 1) {
        if (tid < off) { sh_s[tid] += sh_s[tid + off]; sh_q[tid] += sh_q[tid + off]; }
        __syncthreads();
    }
    if (tid == 0) {
        const float nn = (float)NPIX;
        float m = sh_s[0] / nn;
        float v = sh_q[0] / nn - m * m;
        float inv = rsqrtf(v + 1e-5f);
        float sc = gam[c] * inv;
        scale[c] = sc;
        shift[c] = bet[c] - m * sc;
    }
}

// ---------------- tiled GEMM + fused per-channel partial stats -------------------
// (known-good geometry) 64x64 output tile, 256 threads, 4x4 micro, KC=32.
template<int KDIM, bool AFF>
__global__ void __launch_bounds__(256)
gemm64_kernel(const float* __restrict__ in, const float* __restrict__ W,
              float* __restrict__ out, int Mtot,
              const float* __restrict__ scale, const float* __restrict__ shift,
              float* __restrict__ ps, float* __restrict__ pq)
{
    const int bx    = blockIdx.x;
    const int b     = bx / 49;
    const int ntile = bx % 49;
    const int hw0   = ntile * 64;
    const int m0    = blockIdx.y * 64;
    const int tid   = threadIdx.x;
    const int tx    = tid & 15;
    const int ty    = tid >> 4;

    __shared__ float sW[64][32];
    __shared__ float sX[32][64];

    const float* inb = in + (size_t)b * KDIM * HW_ + hw0;

    float acc[4][4];
#pragma unroll
    for (int i = 0; i < 4; i++)
#pragma unroll
        for (int j = 0; j < 4; j++) acc[i][j] = 0.f;

    for (int c0 = 0; c0 < KDIM; c0 += 32) {
#pragma unroll
        for (int r = 0; r < 2; r++) {
            int f = tid + r * 256;
            int m = f >> 3;
            int ks = f & 7;
            float4 wv = *reinterpret_cast<const float4*>(W + (size_t)(m0 + m) * KDIM + c0 + ks * 4);
            *reinterpret_cast<float4*>(&sW[m][ks * 4]) = wv;
        }
#pragma unroll
        for (int r = 0; r < 2; r++) {
            int f = tid + r * 256;
            int kk = f >> 4;
            int ns = f & 15;
            float4 xv = *reinterpret_cast<const float4*>(inb + (size_t)(c0 + kk) * HW_ + ns * 4);
            if (AFF) {
                float s = scale[c0 + kk], sh = shift[c0 + kk];
                xv.x = fmaxf(xv.x * s + sh, 0.f);
                xv.y = fmaxf(xv.y * s + sh, 0.f);
                xv.z = fmaxf(xv.z * s + sh, 0.f);
                xv.w = fmaxf(xv.w * s + sh, 0.f);
            }
            *reinterpret_cast<float4*>(&sX[kk][ns * 4]) = xv;
        }
        __syncthreads();
#pragma unroll
        for (int kk = 0; kk < 32; kk++) {
            float4 xv = *reinterpret_cast<const float4*>(&sX[kk][tx * 4]);
#pragma unroll
            for (int i = 0; i < 4; i++) {
                float wv = sW[ty + 16 * i][kk];
                acc[i][0] += wv * xv.x;
                acc[i][1] += wv * xv.y;
                acc[i][2] += wv * xv.z;
                acc[i][3] += wv * xv.w;
            }
        }
        __syncthreads();
    }
    float* outb = out + ((size_t)b * Mtot + m0) * HW_ + hw0;
#pragma unroll
    for (int i = 0; i < 4; i++) {
        float4 v = make_float4(acc[i][0], acc[i][1], acc[i][2], acc[i][3]);
        *reinterpret_cast<float4*>(outb + (size_t)(ty + 16 * i) * HW_ + tx * 4) = v;
    }

    // fused per-channel partial (sum, sumsq) over this block's 64 pixels
#pragma unroll
    for (int i = 0; i < 4; i++) {
        float s = acc[i][0] + acc[i][1] + acc[i][2] + acc[i][3];
        float q = acc[i][0] * acc[i][0] + acc[i][1] * acc[i][1]
                + acc[i][2] * acc[i][2] + acc[i][3] * acc[i][3];
#pragma unroll
        for (int off = 8; off > 0; off >>= 1) {
            s += __shfl_down_sync(0xffffffffu, s, off, 16);
            q += __shfl_down_sync(0xffffffffu, q, off, 16);
        }
        if (tx == 0) {
            int ch = m0 + ty + 16 * i;
            ps[(size_t)ch * NB_GEMM + bx] = s;
            pq[(size_t)ch * NB_GEMM + bx] = q;
        }
    }
}

// ---------------- reduce conv (M=16, K=64) + fused partial stats -----------------
__global__ void __launch_bounds__(256)
conv_wr_kernel(const float* __restrict__ in, const float* __restrict__ wr,
               const float* __restrict__ scale, const float* __restrict__ shift,
               float* __restrict__ out, float* __restrict__ ps, float* __restrict__ pq)
{
    __shared__ float swT[64][16];   // transposed weights [c][m]
    __shared__ float ssc[64], ssh[64];
    const int tid = threadIdx.x;
    for (int e = tid; e < 16 * 64; e += 256) { int m = e >> 6, c = e & 63; swT[c][m] = wr[e]; }
    if (tid < 64) { ssc[tid] = scale[tid]; ssh[tid] = shift[tid]; }
    __syncthreads();

    const int p  = blockIdx.x * 256 + tid;
    const int b  = p / HW_, hw = p % HW_;
    const float* pin = in + (size_t)b * MID * HW_ + hw;

    float acc[16];
#pragma unroll
    for (int m = 0; m < 16; m++) acc[m] = 0.f;

#pragma unroll 4
    for (int c = 0; c < 64; c++) {
        float v = fmaxf(pin[(size_t)c * HW_] * ssc[c] + ssh[c], 0.f);
        const float4* w4 = reinterpret_cast<const float4*>(swT[c]);
#pragma unroll
        for (int q = 0; q < 4; q++) {
            float4 w = w4[q];
            acc[4 * q + 0] += w.x * v;
            acc[4 * q + 1] += w.y * v;
            acc[4 * q + 2] += w.z * v;
            acc[4 * q + 3] += w.w * v;
        }
    }
    float* pout = out + (size_t)b * RED * HW_ + hw;
#pragma unroll
    for (int m = 0; m < 16; m++) pout[(size_t)m * HW_] = acc[m];

    const int wid = tid >> 5, lane = tid & 31;
    __shared__ float wsum[8][16], wq[8][16];
#pragma unroll
    for (int m = 0; m < 16; m++) {
        float s = acc[m], q = acc[m] * acc[m];
#pragma unroll
        for (int off = 16; off > 0; off >>= 1) {
            s += __shfl_down_sync(0xffffffffu, s, off);
            q += __shfl_down_sync(0xffffffffu, q, off);
        }
        if (lane == 0) { wsum[wid][m] = s; wq[wid][m] = q; }
    }
    __syncthreads();
    if (tid < 16) {
        float s = 0.f, q = 0.f;
#pragma unroll
        for (int w = 0; w < 8; w++) { s += wsum[w][tid]; q += wq[w][tid]; }
        ps[tid * NB_WR + blockIdx.x] = s;
        pq[tid * NB_WR + blockIdx.x] = q;
    }
}

// ---------------- fused involution v3: R12 structure + vectorized smem -----------
// grid (14 row-tiles, 4 groups, 8 batch), block 224 (= 4 rows x 56 cols).
// z tile stored PIXEL-MAJOR with pad-20 so the 16-channel MAC is 4x LDS.128.
// Per-pixel kernels generated in-register (wk dot via 4x LDS.128 broadcast).
__global__ void __launch_bounds__(224)
involution_kernel(const float* __restrict__ buf1, const float* __restrict__ tin,
                  const float* __restrict__ ws,
                  const float* __restrict__ pst, const float* __restrict__ pqt,
                  const float* __restrict__ gr, const float* __restrict__ br,
                  const float* __restrict__ scale, const float* __restrict__ shift,
                  float* __restrict__ out, float* __restrict__ ps, float* __restrict__ pq)
{
    extern __shared__ float smem[];
    float* s_z  = smem;                     // [620][20] = 12400 (pixel-major, pad 20)
    float* s_t  = smem + 12400;             // [16][224] = 3584 (raw t tile)
    float* s_sw = smem + 12400 + 3584;      // [49][16]  = 784
    float* s_tc = smem + 12400 + 3584 + 784;// [16]
    float* s_th = s_tc + 16;                // [16]

    const int rt = blockIdx.x, g = blockIdx.y, b = blockIdx.z;
    const int r0 = rt * 4;
    const int tid = threadIdx.x;

    // ws rows for this group: [49][16]
    for (int e = tid; e < KK * RED; e += 224) s_sw[e] = ws[(size_t)g * KK * RED + e];

    // fused BNt finalize: 16 channels, 8 lanes each (threads 0..127)
    if (tid < 128) {
        int ch = tid >> 3, part = tid & 7;
        float s = 0.f, q = 0.f;
        for (int i = part; i < NB_WR; i += 8) {
            s += pst[ch * NB_WR + i];
            q += pqt[ch * NB_WR + i];
        }
#pragma unroll
        for (int off = 4; off > 0; off >>= 1) {
            s += __shfl_down_sync(0xffffffffu, s, off, 8);
            q += __shfl_down_sync(0xffffffffu, q, off, 8);
        }
        if (part == 0) {
            const float nn = (float)NPIX;
            float m = s / nn;
            float v = q / nn - m * m;
            float sc = gr[ch] * rsqrtf(v + 1e-5f);
            s_tc[ch] = sc;
            s_th[ch] = br[ch] - m * sc;
        }
    }

    // raw t tile: [16][224]
    {
        const float* src = tin + (size_t)b * RED * HW_ + r0 * 56;
#pragma unroll
        for (int c = 0; c < 16; c++)
            s_t[c * 224 + tid] = src[(size_t)c * HW_ + tid];
    }

    // z1 tile with halo, BN1 affine + ReLU on load; PIXEL-MAJOR pad-20 layout.
    // Global reads stay coalesced (c outer); STS has bounded 4-way conflicts.
    {
        const float* src = buf1 + ((size_t)b * MID + g * GC_) * HW_;
        for (int e = tid; e < 16 * 620; e += 224) {
            int c   = e / 620;
            int p   = e - c * 620;
            int ry  = p / 62;
            int cx  = p - ry * 62;
            int gy  = r0 - 3 + ry;
            int gx  = cx - 3;
            float v = 0.f;
            if (gy >= 0 && gy < 56 && gx >= 0 && gx < 56) {
                int ch = g * GC_ + c;
                v = fmaxf(src[(size_t)c * HW_ + gy * 56 + gx] * scale[ch] + shift[ch], 0.f);
            }
            s_z[p * 20 + c] = v;
        }
    }
    __syncthreads();

    // per-thread t vector with BNt affine + ReLU
    float t[16];
#pragma unroll
    for (int c = 0; c < 16; c++)
        t[c] = fmaxf(s_t[c * 224 + tid] * s_tc[c] + s_th[c], 0.f);

    const int row = tid / 56, col = tid % 56;
    float acc[16];
#pragma unroll
    for (int c = 0; c < 16; c++) acc[c] = 0.f;

#pragma unroll 7
    for (int k = 0; k < 49; k++) {
        // kernel value for this pixel/tap: dot(ws[k], t) via vector loads (broadcast)
        const float4* w4 = reinterpret_cast<const float4*>(&s_sw[k * 16]);
        float4 wa = w4[0], wb = w4[1], wc = w4[2], wd = w4[3];
        float wk = wa.x * t[0]  + wa.y * t[1]  + wa.z * t[2]  + wa.w * t[3]
                 + wb.x * t[4]  + wb.y * t[5]  + wb.z * t[6]  + wb.w * t[7]
                 + wc.x * t[8]  + wc.y * t[9]  + wc.z * t[10] + wc.w * t[11]
                 + wd.x * t[12] + wd.y * t[13] + wd.z * t[14] + wd.w * t[15];

        int dy = k / 7, dx = k - dy * 7;
        const float4* zp = reinterpret_cast<const float4*>(
            &s_z[((row + dy) * 62 + (col + dx)) * 20]);
        float4 z0 = zp[0], z1 = zp[1], z2 = zp[2], z3 = zp[3];
        acc[0]  += wk * z0.x;  acc[1]  += wk * z0.y;  acc[2]  += wk * z0.z;  acc[3]  += wk * z0.w;
        acc[4]  += wk * z1.x;  acc[5]  += wk * z1.y;  acc[6]  += wk * z1.z;  acc[7]  += wk * z1.w;
        acc[8]  += wk * z2.x;  acc[9]  += wk * z2.y;  acc[10] += wk * z2.z;  acc[11] += wk * z2.w;
        acc[12] += wk * z3.x;  acc[13] += wk * z3.y;  acc[14] += wk * z3.z;  acc[15] += wk * z3.w;
    }

    float* dst = out + ((size_t)b * MID + g * GC_) * HW_ + r0 * 56 + tid;
#pragma unroll
    for (int c = 0; c < 16; c++) dst[(size_t)c * HW_] = acc[c];

    // fused BN2 partial stats (7 warps)
    const int wid = tid >> 5, lane = tid & 31;
    __shared__ float wsum[7][16], wq[7][16];
#pragma unroll
    for (int c = 0; c < 16; c++) {
        float s = acc[c], q = acc[c] * acc[c];
#pragma unroll
        for (int off = 16; off > 0; off >>= 1) {
            s += __shfl_down_sync(0xffffffffu, s, off);
            q += __shfl_down_sync(0xffffffffu, q, off);
        }
        if (lane == 0) { wsum[wid][c] = s; wq[wid][c] = q; }
    }
    __syncthreads();
    if (tid < 16) {
        float s = 0.f, q = 0.f;
#pragma unroll
        for (int w = 0; w < 7; w++) { s += wsum[w][tid]; q += wq[w][tid]; }
        int ch = g * GC_ + tid;
        int slot = b * 14 + rt;
        ps[(size_t)ch * NB_INV + slot] = s;
        pq[(size_t)ch * NB_INV + slot] = q;
    }
}

// ---------------- epilogue: relu(bn(y3) + x), fused BN3 finalize ------------------
__global__ void __launch_bounds__(256)
final_kernel(const float4* __restrict__ y3, const float4* __restrict__ xin,
             const float* __restrict__ ps, const float* __restrict__ pq,
             const float* __restrict__ g3, const float* __restrict__ b3,
             float4* __restrict__ out)
{
    const int bc = blockIdx.x;          // b*256 + c
    const int c  = bc & 255;
    const int tid = threadIdx.x;

    __shared__ float sh_s[256], sh_q[256];
    __shared__ float s_sc, s_sh;
    {
        float s = 0.f, q = 0.f;
        for (int i = tid; i < NB_GEMM; i += 256) {
            s += ps[(size_t)c * NB_GEMM + i];
            q += pq[(size_t)c * NB_GEMM + i];
        }
        sh_s[tid] = s; sh_q[tid] = q;
        __syncthreads();
        for (int off = 128; off > 0; off >>= 1) {
            if (tid < off) { sh_s[tid] += sh_s[tid + off]; sh_q[tid] += sh_q[tid + off]; }
            __syncthreads();
        }
        if (tid == 0) {
            const float nn = (float)NPIX;
            float m = sh_s[0] / nn;
            float v = sh_q[0] / nn - m * m;
            float sc = g3[c] * rsqrtf(v + 1e-5f);
            s_sc = sc;
            s_sh = b3[c] - m * sc;
        }
        __syncthreads();
    }
    const float s = s_sc, sh = s_sh;
    const size_t base = (size_t)bc * 784;      // 784 float4 per (b,c)
    for (int j = tid; j < 784; j += 256) {
        float4 a = y3[base + j], r0 = xin[base + j], r;
        r.x = fmaxf(a.x * s + sh + r0.x, 0.f);
        r.y = fmaxf(a.y * s + sh + r0.y, 0.f);
        r.z = fmaxf(a.z * s + sh + r0.z, 0.f);
        r.w = fmaxf(a.w * s + sh + r0.w, 0.f);
        out[base + j] = r;
    }
}

// ---------------- launch ---------------------------------------------------------
static void* sym_addr(const void* s) { void* p = nullptr; cudaGetSymbolAddress(&p, s); return p; }

extern "C" void kernel_launch(void* const* d_in, const int* in_sizes, int n_in,
                              void* d_out, int out_size)
{
    const float* x  = (const float*)d_in[0];
    const float* w1 = (const float*)d_in[1];
    const float* g1 = (const float*)d_in[2];
    const float* b1 = (const float*)d_in[3];
    const float* wr = (const float*)d_in[4];
    const float* gr = (const float*)d_in[5];
    const float* br = (const float*)d_in[6];
    const float* ws = (const float*)d_in[7];
    const float* g2 = (const float*)d_in[8];
    const float* b2 = (const float*)d_in[9];
    const float* w3 = (const float*)d_in[10];
    const float* g3 = (const float*)d_in[11];
    const float* b3 = (const float*)d_in[12];
    float* out = (float*)d_out;

    float* buf1 = (float*)sym_addr(g_buf1);
    float* tbuf = (float*)sym_addr(g_t);
    float* invb = (float*)sym_addr(g_inv);
    float* y3   = (float*)sym_addr(g_y3);
    float* ps1 = (float*)sym_addr(g_ps1);  float* pq1 = (float*)sym_addr(g_pq1);
    float* pst = (float*)sym_addr(g_pst);  float* pqt = (float*)sym_addr(g_pqt);
    float* ps2 = (float*)sym_addr(g_ps2);  float* pq2 = (float*)sym_addr(g_pq2);
    float* ps3 = (float*)sym_addr(g_ps3);  float* pq3 = (float*)sym_addr(g_pq3);
    float* sc1 = (float*)sym_addr(g_sc1);  float* sh1 = (float*)sym_addr(g_sh1);
    float* sc2 = (float*)sym_addr(g_sc2);  float* sh2 = (float*)sym_addr(g_sh2);

    // smem: 12400 (z pad-20) + 3584 (t) + 784 (ws) + 32 (bn_t) floats = 67200 bytes
    const int inv_smem = (12400 + 3584 + 784 + 32) * 4;
    cudaFuncSetAttribute(involution_kernel, cudaFuncAttributeMaxDynamicSharedMemorySize, inv_smem);

    // 1) conv1: [8,256,HW] -> buf1 [8,64,HW] (+BN1 partials)
    gemm64_kernel<256, false><<<dim3(NB_GEMM, 1), 256>>>(x, w1, buf1, MID, nullptr, nullptr, ps1, pq1);
    // 2) BN1 finalize (dual consumer: conv_wr + involution)
    finalize_kernel<<<MID, 256>>>(ps1, pq1, NB_GEMM, g1, b1, sc1, sh1);
    // 3) reduce conv: relu(bn(buf1)) -> t (+BNt partials)
    conv_wr_kernel<<<NB_WR, 256>>>(buf1, wr, sc1, sh1, tbuf, pst, pqt);
    // 4) fused involution v3 (vectorized smem) -> inv (+BN2 partials)
    involution_kernel<<<dim3(14, GRP, B_), 224, inv_smem>>>(buf1, tbuf, ws, pst, pqt, gr, br,
                                                            sc1, sh1, invb, ps2, pq2);
    // 5) BN2 finalize
    finalize_kernel<<<MID, 256>>>(ps2, pq2, NB_INV, g2, b2, sc2, sh2);
    // 6) conv3: relu(bn(inv)) -> y3 [8,256,HW] (+BN3 partials)
    gemm64_kernel<64, true><<<dim3(NB_GEMM, 4), 256>>>(invb, w3, y3, C1, sc2, sh2, ps3, pq3);
    // 7) epilogue (fused BN3 finalize): relu(bn(y3) + x)
    final_kernel<<<B_ * C1, 256>>>((const float4*)y3, (const float4*)x, ps3, pq3, g3, b3, (float4*)out);
}

// round 15
// speedup vs baseline: 1.1019x; 1.0116x over previous
#include <cuda_runtime.h>
#include <cuda_bf16.h>
#include <cstddef>

// Problem constants
#define B_   8
#define HW_  3136          // 56*56
#define NPIX (B_*HW_)      // 25088
#define C1   256
#define MID  64
#define RED  16
#define GRP  4
#define GC_  16
#define KK   49            // 7*7
#define GKK  196           // 4*49

#define NB_GEMM 392        // 49*8 pixel-tile blocks for gemm
#define NB_WR   98         // NPIX/256
#define NB_INV  112        // 14*8 per channel-group

// ---------------- scratch (device globals; no allocation allowed) ----------------
__device__ float g_buf1[B_ * MID * HW_];   // conv1 raw output
__device__ float g_t   [B_ * RED * HW_];   // reduce conv raw output
__device__ float g_inv [B_ * MID * HW_];   // involution raw output
__device__ float g_y3  [B_ * C1  * HW_];   // conv3 raw output
__device__ float g_ps1[MID * NB_GEMM], g_pq1[MID * NB_GEMM];
__device__ float g_pst[RED * NB_WR],   g_pqt[RED * NB_WR];
__device__ float g_ps2[MID * NB_INV],  g_pq2[MID * NB_INV];
__device__ float g_ps3[C1  * NB_GEMM], g_pq3[C1  * NB_GEMM];
__device__ float g_sc1[MID],  g_sh1[MID];
__device__ float g_sc2[MID],  g_sh2[MID];

// ---------------- finalize: combine per-block partials into scale/shift ----------
__global__ void finalize_kernel(const float* __restrict__ ps, const float* __restrict__ pq,
                                int n, const float* __restrict__ gam, const float* __restrict__ bet,
                                float* __restrict__ scale, float* __restrict__ shift)
{
    const int c = blockIdx.x;
    const int tid = threadIdx.x;
    float s = 0.f, q = 0.f;
    for (int i = tid; i < n; i += 256) { s += ps[c * n + i]; q += pq[c * n + i]; }
    __shared__ float sh_s[256], sh_q[256];
    sh_s[tid] = s; sh_q[tid] = q;
    __syncthreads();
    for (int off = 128; off > 0; off >>= 1) {
        if (tid < off) { sh_s[tid] += sh_s[tid + off]; sh_q[tid] += sh_q[tid + off]; }
        __syncthreads();
    }
    if (tid == 0) {
        const float nn = (float)NPIX;
        float m = sh_s[0] / nn;
        float v = sh_q[0] / nn - m * m;
        float inv = rsqrtf(v + 1e-5f);
        float sc = gam[c] * inv;
        scale[c] = sc;
        shift[c] = bet[c] - m * sc;
    }
}

// ---------------- tiled GEMM + fused per-channel partial stats -------------------
// (known-good geometry) 64x64 output tile, 256 threads, 4x4 micro, KC=32.
template<int KDIM, bool AFF>
__global__ void __launch_bounds__(256)
gemm64_kernel(const float* __restrict__ in, const float* __restrict__ W,
              float* __restrict__ out, int Mtot,
              const float* __restrict__ scale, const float* __restrict__ shift,
              float* __restrict__ ps, float* __restrict__ pq)
{
    const int bx    = blockIdx.x;
    const int b     = bx / 49;
    const int ntile = bx % 49;
    const int hw0   = ntile * 64;
    const int m0    = blockIdx.y * 64;
    const int tid   = threadIdx.x;
    const int tx    = tid & 15;
    const int ty    = tid >> 4;

    __shared__ float sW[64][32];
    __shared__ float sX[32][64];

    const float* inb = in + (size_t)b * KDIM * HW_ + hw0;

    float acc[4][4];
#pragma unroll
    for (int i = 0; i < 4; i++)
#pragma unroll
        for (int j = 0; j < 4; j++) acc[i][j] = 0.f;

    for (int c0 = 0; c0 < KDIM; c0 += 32) {
#pragma unroll
        for (int r = 0; r < 2; r++) {
            int f = tid + r * 256;
            int m = f >> 3;
            int ks = f & 7;
            float4 wv = *reinterpret_cast<const float4*>(W + (size_t)(m0 + m) * KDIM + c0 + ks * 4);
            *reinterpret_cast<float4*>(&sW[m][ks * 4]) = wv;
        }
#pragma unroll
        for (int r = 0; r < 2; r++) {
            int f = tid + r * 256;
            int kk = f >> 4;
            int ns = f & 15;
            float4 xv = *reinterpret_cast<const float4*>(inb + (size_t)(c0 + kk) * HW_ + ns * 4);
            if (AFF) {
                float s = scale[c0 + kk], sh = shift[c0 + kk];
                xv.x = fmaxf(xv.x * s + sh, 0.f);
                xv.y = fmaxf(xv.y * s + sh, 0.f);
                xv.z = fmaxf(xv.z * s + sh, 0.f);
                xv.w = fmaxf(xv.w * s + sh, 0.f);
            }
            *reinterpret_cast<float4*>(&sX[kk][ns * 4]) = xv;
        }
        __syncthreads();
#pragma unroll
        for (int kk = 0; kk < 32; kk++) {
            float4 xv = *reinterpret_cast<const float4*>(&sX[kk][tx * 4]);
#pragma unroll
            for (int i = 0; i < 4; i++) {
                float wv = sW[ty + 16 * i][kk];
                acc[i][0] += wv * xv.x;
                acc[i][1] += wv * xv.y;
                acc[i][2] += wv * xv.z;
                acc[i][3] += wv * xv.w;
            }
        }
        __syncthreads();
    }
    float* outb = out + ((size_t)b * Mtot + m0) * HW_ + hw0;
#pragma unroll
    for (int i = 0; i < 4; i++) {
        float4 v = make_float4(acc[i][0], acc[i][1], acc[i][2], acc[i][3]);
        *reinterpret_cast<float4*>(outb + (size_t)(ty + 16 * i) * HW_ + tx * 4) = v;
    }

    // fused per-channel partial (sum, sumsq) over this block's 64 pixels
#pragma unroll
    for (int i = 0; i < 4; i++) {
        float s = acc[i][0] + acc[i][1] + acc[i][2] + acc[i][3];
        float q = acc[i][0] * acc[i][0] + acc[i][1] * acc[i][1]
                + acc[i][2] * acc[i][2] + acc[i][3] * acc[i][3];
#pragma unroll
        for (int off = 8; off > 0; off >>= 1) {
            s += __shfl_down_sync(0xffffffffu, s, off, 16);
            q += __shfl_down_sync(0xffffffffu, q, off, 16);
        }
        if (tx == 0) {
            int ch = m0 + ty + 16 * i;
            ps[(size_t)ch * NB_GEMM + bx] = s;
            pq[(size_t)ch * NB_GEMM + bx] = q;
        }
    }
}

// ---------------- reduce conv (M=16, K=64) + fused partial stats -----------------
__global__ void __launch_bounds__(256)
conv_wr_kernel(const float* __restrict__ in, const float* __restrict__ wr,
               const float* __restrict__ scale, const float* __restrict__ shift,
               float* __restrict__ out, float* __restrict__ ps, float* __restrict__ pq)
{
    __shared__ float swT[64][16];   // transposed weights [c][m]
    __shared__ float ssc[64], ssh[64];
    const int tid = threadIdx.x;
    for (int e = tid; e < 16 * 64; e += 256) { int m = e >> 6, c = e & 63; swT[c][m] = wr[e]; }
    if (tid < 64) { ssc[tid] = scale[tid]; ssh[tid] = shift[tid]; }
    __syncthreads();

    const int p  = blockIdx.x * 256 + tid;
    const int b  = p / HW_, hw = p % HW_;
    const float* pin = in + (size_t)b * MID * HW_ + hw;

    float acc[16];
#pragma unroll
    for (int m = 0; m < 16; m++) acc[m] = 0.f;

#pragma unroll 4
    for (int c = 0; c < 64; c++) {
        float v = fmaxf(pin[(size_t)c * HW_] * ssc[c] + ssh[c], 0.f);
        const float4* w4 = reinterpret_cast<const float4*>(swT[c]);
#pragma unroll
        for (int q = 0; q < 4; q++) {
            float4 w = w4[q];
            acc[4 * q + 0] += w.x * v;
            acc[4 * q + 1] += w.y * v;
            acc[4 * q + 2] += w.z * v;
            acc[4 * q + 3] += w.w * v;
        }
    }
    float* pout = out + (size_t)b * RED * HW_ + hw;
#pragma unroll
    for (int m = 0; m < 16; m++) pout[(size_t)m * HW_] = acc[m];

    const int wid = tid >> 5, lane = tid & 31;
    __shared__ float wsum[8][16], wq[8][16];
#pragma unroll
    for (int m = 0; m < 16; m++) {
        float s = acc[m], q = acc[m] * acc[m];
#pragma unroll
        for (int off = 16; off > 0; off >>= 1) {
            s += __shfl_down_sync(0xffffffffu, s, off);
            q += __shfl_down_sync(0xffffffffu, q, off);
        }
        if (lane == 0) { wsum[wid][m] = s; wq[wid][m] = q; }
    }
    __syncthreads();
    if (tid < 16) {
        float s = 0.f, q = 0.f;
#pragma unroll
        for (int w = 0; w < 8; w++) { s += wsum[w][tid]; q += wq[w][tid]; }
        ps[tid * NB_WR + blockIdx.x] = s;
        pq[tid * NB_WR + blockIdx.x] = q;
    }
}

// ---------------- fused involution v3: R12 structure + vectorized smem -----------
// grid (14 row-tiles, 4 groups, 8 batch), block 224 (= 4 rows x 56 cols).
// z tile stored PIXEL-MAJOR with pad-20 so the 16-channel MAC is 4x LDS.128.
// Per-pixel kernels generated in-register (wk dot via 4x LDS.128 broadcast).
__global__ void __launch_bounds__(224)
involution_kernel(const float* __restrict__ buf1, const float* __restrict__ tin,
                  const float* __restrict__ ws,
                  const float* __restrict__ pst, const float* __restrict__ pqt,
                  const float* __restrict__ gr, const float* __restrict__ br,
                  const float* __restrict__ scale, const float* __restrict__ shift,
                  float* __restrict__ out, float* __restrict__ ps, float* __restrict__ pq)
{
    extern __shared__ float smem[];
    float* s_z  = smem;                     // [620][20] = 12400 (pixel-major, pad 20)
    float* s_t  = smem + 12400;             // [16][224] = 3584 (raw t tile)
    float* s_sw = smem + 12400 + 3584;      // [49][16]  = 784
    float* s_tc = smem + 12400 + 3584 + 784;// [16]
    float* s_th = s_tc + 16;                // [16]

    const int rt = blockIdx.x, g = blockIdx.y, b = blockIdx.z;
    const int r0 = rt * 4;
    const int tid = threadIdx.x;

    // ws rows for this group: [49][16]
    for (int e = tid; e < KK * RED; e += 224) s_sw[e] = ws[(size_t)g * KK * RED + e];

    // fused BNt finalize: 16 channels, 8 lanes each (threads 0..127)
    if (tid < 128) {
        int ch = tid >> 3, part = tid & 7;
        float s = 0.f, q = 0.f;
        for (int i = part; i < NB_WR; i += 8) {
            s += pst[ch * NB_WR + i];
            q += pqt[ch * NB_WR + i];
        }
#pragma unroll
        for (int off = 4; off > 0; off >>= 1) {
            s += __shfl_down_sync(0xffffffffu, s, off, 8);
            q += __shfl_down_sync(0xffffffffu, q, off, 8);
        }
        if (part == 0) {
            const float nn = (float)NPIX;
            float m = s / nn;
            float v = q / nn - m * m;
            float sc = gr[ch] * rsqrtf(v + 1e-5f);
            s_tc[ch] = sc;
            s_th[ch] = br[ch] - m * sc;
        }
    }

    // raw t tile: [16][224]
    {
        const float* src = tin + (size_t)b * RED * HW_ + r0 * 56;
#pragma unroll
        for (int c = 0; c < 16; c++)
            s_t[c * 224 + tid] = src[(size_t)c * HW_ + tid];
    }

    // z1 tile with halo, BN1 affine + ReLU on load; PIXEL-MAJOR pad-20 layout.
    // Global reads stay coalesced (c outer); STS has bounded 4-way conflicts.
    {
        const float* src = buf1 + ((size_t)b * MID + g * GC_) * HW_;
        for (int e = tid; e < 16 * 620; e += 224) {
            int c   = e / 620;
            int p   = e - c * 620;
            int ry  = p / 62;
            int cx  = p - ry * 62;
            int gy  = r0 - 3 + ry;
            int gx  = cx - 3;
            float v = 0.f;
            if (gy >= 0 && gy < 56 && gx >= 0 && gx < 56) {
                int ch = g * GC_ + c;
                v = fmaxf(src[(size_t)c * HW_ + gy * 56 + gx] * scale[ch] + shift[ch], 0.f);
            }
            s_z[p * 20 + c] = v;
        }
    }
    __syncthreads();

    // per-thread t vector with BNt affine + ReLU
    float t[16];
#pragma unroll
    for (int c = 0; c < 16; c++)
        t[c] = fmaxf(s_t[c * 224 + tid] * s_tc[c] + s_th[c], 0.f);

    const int row = tid / 56, col = tid % 56;
    float acc[16];
#pragma unroll
    for (int c = 0; c < 16; c++) acc[c] = 0.f;

#pragma unroll 7
    for (int k = 0; k < 49; k++) {
        // kernel value for this pixel/tap: dot(ws[k], t) via vector loads (broadcast)
        const float4* w4 = reinterpret_cast<const float4*>(&s_sw[k * 16]);
        float4 wa = w4[0], wb = w4[1], wc = w4[2], wd = w4[3];
        float wk = wa.x * t[0]  + wa.y * t[1]  + wa.z * t[2]  + wa.w * t[3]
                 + wb.x * t[4]  + wb.y * t[5]  + wb.z * t[6]  + wb.w * t[7]
                 + wc.x * t[8]  + wc.y * t[9]  + wc.z * t[10] + wc.w * t[11]
                 + wd.x * t[12] + wd.y * t[13] + wd.z * t[14] + wd.w * t[15];

        int dy = k / 7, dx = k - dy * 7;
        const float4* zp = reinterpret_cast<const float4*>(
            &s_z[((row + dy) * 62 + (col + dx)) * 20]);
        float4 z0 = zp[0], z1 = zp[1], z2 = zp[2], z3 = zp[3];
        acc[0]  += wk * z0.x;  acc[1]  += wk * z0.y;  acc[2]  += wk * z0.z;  acc[3]  += wk * z0.w;
        acc[4]  += wk * z1.x;  acc[5]  += wk * z1.y;  acc[6]  += wk * z1.z;  acc[7]  += wk * z1.w;
        acc[8]  += wk * z2.x;  acc[9]  += wk * z2.y;  acc[10] += wk * z2.z;  acc[11] += wk * z2.w;
        acc[12] += wk * z3.x;  acc[13] += wk * z3.y;  acc[14] += wk * z3.z;  acc[15] += wk * z3.w;
    }

    float* dst = out + ((size_t)b * MID + g * GC_) * HW_ + r0 * 56 + tid;
#pragma unroll
    for (int c = 0; c < 16; c++) dst[(size_t)c * HW_] = acc[c];

    // fused BN2 partial stats (7 warps)
    const int wid = tid >> 5, lane = tid & 31;
    __shared__ float wsum[7][16], wq[7][16];
#pragma unroll
    for (int c = 0; c < 16; c++) {
        float s = acc[c], q = acc[c] * acc[c];
#pragma unroll
        for (int off = 16; off > 0; off >>= 1) {
            s += __shfl_down_sync(0xffffffffu, s, off);
            q += __shfl_down_sync(0xffffffffu, q, off);
        }
        if (lane == 0) { wsum[wid][c] = s; wq[wid][c] = q; }
    }
    __syncthreads();
    if (tid < 16) {
        float s = 0.f, q = 0.f;
#pragma unroll
        for (int w = 0; w < 7; w++) { s += wsum[w][tid]; q += wq[w][tid]; }
        int ch = g * GC_ + tid;
        int slot = b * 14 + rt;
        ps[(size_t)ch * NB_INV + slot] = s;
        pq[(size_t)ch * NB_INV + slot] = q;
    }
}

// ---------------- epilogue: relu(bn(y3) + x), fused BN3 finalize ------------------
__global__ void __launch_bounds__(256)
final_kernel(const float4* __restrict__ y3, const float4* __restrict__ xin,
             const float* __restrict__ ps, const float* __restrict__ pq,
             const float* __restrict__ g3, const float* __restrict__ b3,
             float4* __restrict__ out)
{
    const int bc = blockIdx.x;          // b*256 + c
    const int c  = bc & 255;
    const int tid = threadIdx.x;

    __shared__ float sh_s[256], sh_q[256];
    __shared__ float s_sc, s_sh;
    {
        float s = 0.f, q = 0.f;
        for (int i = tid; i < NB_GEMM; i += 256) {
            s += ps[(size_t)c * NB_GEMM + i];
            q += pq[(size_t)c * NB_GEMM + i];
        }
        sh_s[tid] = s; sh_q[tid] = q;
        __syncthreads();
        for (int off = 128; off > 0; off >>= 1) {
            if (tid < off) { sh_s[tid] += sh_s[tid + off]; sh_q[tid] += sh_q[tid + off]; }
            __syncthreads();
        }
        if (tid == 0) {
            const float nn = (float)NPIX;
            float m = sh_s[0] / nn;
            float v = sh_q[0] / nn - m * m;
            float sc = g3[c] * rsqrtf(v + 1e-5f);
            s_sc = sc;
            s_sh = b3[c] - m * sc;
        }
        __syncthreads();
    }
    const float s = s_sc, sh = s_sh;
    const size_t base = (size_t)bc * 784;      // 784 float4 per (b,c)
    for (int j = tid; j < 784; j += 256) {
        float4 a = y3[base + j], r0 = xin[base + j], r;
        r.x = fmaxf(a.x * s + sh + r0.x, 0.f);
        r.y = fmaxf(a.y * s + sh + r0.y, 0.f);
        r.z = fmaxf(a.z * s + sh + r0.z, 0.f);
        r.w = fmaxf(a.w * s + sh + r0.w, 0.f);
        out[base + j] = r;
    }
}

// ---------------- launch ---------------------------------------------------------
static void* sym_addr(const void* s) { void* p = nullptr; cudaGetSymbolAddress(&p, s); return p; }

extern "C" void kernel_launch(void* const* d_in, const int* in_sizes, int n_in,
                              void* d_out, int out_size)
{
    const float* x  = (const float*)d_in[0];
    const float* w1 = (const float*)d_in[1];
    const float* g1 = (const float*)d_in[2];
    const float* b1 = (const float*)d_in[3];
    const float* wr = (const float*)d_in[4];
    const float* gr = (const float*)d_in[5];
    const float* br = (const float*)d_in[6];
    const float* ws = (const float*)d_in[7];
    const float* g2 = (const float*)d_in[8];
    const float* b2 = (const float*)d_in[9];
    const float* w3 = (const float*)d_in[10];
    const float* g3 = (const float*)d_in[11];
    const float* b3 = (const float*)d_in[12];
    float* out = (float*)d_out;

    float* buf1 = (float*)sym_addr(g_buf1);
    float* tbuf = (float*)sym_addr(g_t);
    float* invb = (float*)sym_addr(g_inv);
    float* y3   = (float*)sym_addr(g_y3);
    float* ps1 = (float*)sym_addr(g_ps1);  float* pq1 = (float*)sym_addr(g_pq1);
    float* pst = (float*)sym_addr(g_pst);  float* pqt = (float*)sym_addr(g_pqt);
    float* ps2 = (float*)sym_addr(g_ps2);  float* pq2 = (float*)sym_addr(g_pq2);
    float* ps3 = (float*)sym_addr(g_ps3);  float* pq3 = (float*)sym_addr(g_pq3);
    float* sc1 = (float*)sym_addr(g_sc1);  float* sh1 = (float*)sym_addr(g_sh1);
    float* sc2 = (float*)sym_addr(g_sc2);  float* sh2 = (float*)sym_addr(g_sh2);

    // smem: 12400 (z pad-20) + 3584 (t) + 784 (ws) + 32 (bn_t) floats = 67200 bytes
    const int inv_smem = (12400 + 3584 + 784 + 32) * 4;
    cudaFuncSetAttribute(involution_kernel, cudaFuncAttributeMaxDynamicSharedMemorySize, inv_smem);

    // 1) conv1: [8,256,HW] -> buf1 [8,64,HW] (+BN1 partials)
    gemm64_kernel<256, false><<<dim3(NB_GEMM, 1), 256>>>(x, w1, buf1, MID, nullptr, nullptr, ps1, pq1);
    // 2) BN1 finalize (dual consumer: conv_wr + involution)
    finalize_kernel<<<MID, 256>>>(ps1, pq1, NB_GEMM, g1, b1, sc1, sh1);
    // 3) reduce conv: relu(bn(buf1)) -> t (+BNt partials)
    conv_wr_kernel<<<NB_WR, 256>>>(buf1, wr, sc1, sh1, tbuf, pst, pqt);
    // 4) fused involution v3 (vectorized smem) -> inv (+BN2 partials)
    involution_kernel<<<dim3(14, GRP, B_), 224, inv_smem>>>(buf1, tbuf, ws, pst, pqt, gr, br,
                                                            sc1, sh1, invb, ps2, pq2);
    // 5) BN2 finalize
    finalize_kernel<<<MID, 256>>>(ps2, pq2, NB_INV, g2, b2, sc2, sh2);
    // 6) conv3: relu(bn(inv)) -> y3 [8,256,HW] (+BN3 partials)
    gemm64_kernel<64, true><<<dim3(NB_GEMM, 4), 256>>>(invb, w3, y3, C1, sc2, sh2, ps3, pq3);
    // 7) epilogue (fused BN3 finalize): relu(bn(y3) + x)
    final_kernel<<<B_ * C1, 256>>>((const float4*)y3, (const float4*)x, ps3, pq3, g3, b3, (float4*)out);
}

// round 16
// speedup vs baseline: 1.1044x; 1.0023x over previous
#include <cuda_runtime.h>
#include <cuda_bf16.h>
#include <cstddef>

// Problem constants
#define B_   8
#define HW_  3136          // 56*56
#define NPIX (B_*HW_)      // 25088
#define C1   256
#define MID  64
#define RED  16
#define GRP  4
#define GC_  16
#define KK   49            // 7*7
#define GKK  196           // 4*49

#define NB_GEMM 392        // 49*8 pixel-tile blocks for gemm
#define NB_WR   98         // NPIX/256
#define NB_INV  112        // 14*8 per channel-group

// ---------------- scratch (device globals; no allocation allowed) ----------------
__device__ float g_buf1[B_ * MID * HW_];   // conv1 raw output
__device__ float g_t   [B_ * RED * HW_];   // reduce conv raw output
__device__ float g_inv [B_ * MID * HW_];   // involution raw output
__device__ float g_y3  [B_ * C1  * HW_];   // conv3 raw output
__device__ float g_ps1[MID * NB_GEMM], g_pq1[MID * NB_GEMM];
__device__ float g_pst[RED * NB_WR],   g_pqt[RED * NB_WR];
__device__ float g_ps2[MID * NB_INV],  g_pq2[MID * NB_INV];
__device__ float g_ps3[C1  * NB_GEMM], g_pq3[C1  * NB_GEMM];
__device__ float g_sc1[MID],  g_sh1[MID];
__device__ float g_sc2[MID],  g_sh2[MID];

// ---------------- finalize: combine per-block partials into scale/shift ----------
__global__ void finalize_kernel(const float* __restrict__ ps, const float* __restrict__ pq,
                                int n, const float* __restrict__ gam, const float* __restrict__ bet,
                                float* __restrict__ scale, float* __restrict__ shift)
{
    const int c = blockIdx.x;
    const int tid = threadIdx.x;
    float s = 0.f, q = 0.f;
    for (int i = tid; i < n; i += 256) { s += ps[c * n + i]; q += pq[c * n + i]; }
    __shared__ float sh_s[256], sh_q[256];
    sh_s[tid] = s; sh_q[tid] = q;
    __syncthreads();
    for (int off = 128; off > 0; off >>= 1) {
        if (tid < off) { sh_s[tid] += sh_s[tid + off]; sh_q[tid] += sh_q[tid + off]; }
        __syncthreads();
    }
    if (tid == 0) {
        const float nn = (float)NPIX;
        float m = sh_s[0] / nn;
        float v = sh_q[0] / nn - m * m;
        float inv = rsqrtf(v + 1e-5f);
        float sc = gam[c] * inv;
        scale[c] = sc;
        shift[c] = bet[c] - m * sc;
    }
}

// ---------------- tiled GEMM + fused per-channel partial stats -------------------
// (known-good geometry) 64x64 output tile, 256 threads, 4x4 micro, KC=32.
template<int KDIM, bool AFF>
__global__ void __launch_bounds__(256)
gemm64_kernel(const float* __restrict__ in, const float* __restrict__ W,
              float* __restrict__ out, int Mtot,
              const float* __restrict__ scale, const float* __restrict__ shift,
              float* __restrict__ ps, float* __restrict__ pq)
{
    const int bx    = blockIdx.x;
    const int b     = bx / 49;
    const int ntile = bx % 49;
    const int hw0   = ntile * 64;
    const int m0    = blockIdx.y * 64;
    const int tid   = threadIdx.x;
    const int tx    = tid & 15;
    const int ty    = tid >> 4;

    __shared__ float sW[64][32];
    __shared__ float sX[32][64];

    const float* inb = in + (size_t)b * KDIM * HW_ + hw0;

    float acc[4][4];
#pragma unroll
    for (int i = 0; i < 4; i++)
#pragma unroll
        for (int j = 0; j < 4; j++) acc[i][j] = 0.f;

    for (int c0 = 0; c0 < KDIM; c0 += 32) {
#pragma unroll
        for (int r = 0; r < 2; r++) {
            int f = tid + r * 256;
            int m = f >> 3;
            int ks = f & 7;
            float4 wv = *reinterpret_cast<const float4*>(W + (size_t)(m0 + m) * KDIM + c0 + ks * 4);
            *reinterpret_cast<float4*>(&sW[m][ks * 4]) = wv;
        }
#pragma unroll
        for (int r = 0; r < 2; r++) {
            int f = tid + r * 256;
            int kk = f >> 4;
            int ns = f & 15;
            float4 xv = *reinterpret_cast<const float4*>(inb + (size_t)(c0 + kk) * HW_ + ns * 4);
            if (AFF) {
                float s = scale[c0 + kk], sh = shift[c0 + kk];
                xv.x = fmaxf(xv.x * s + sh, 0.f);
                xv.y = fmaxf(xv.y * s + sh, 0.f);
                xv.z = fmaxf(xv.z * s + sh, 0.f);
                xv.w = fmaxf(xv.w * s + sh, 0.f);
            }
            *reinterpret_cast<float4*>(&sX[kk][ns * 4]) = xv;
        }
        __syncthreads();
#pragma unroll
        for (int kk = 0; kk < 32; kk++) {
            float4 xv = *reinterpret_cast<const float4*>(&sX[kk][tx * 4]);
#pragma unroll
            for (int i = 0; i < 4; i++) {
                float wv = sW[ty + 16 * i][kk];
                acc[i][0] += wv * xv.x;
                acc[i][1] += wv * xv.y;
                acc[i][2] += wv * xv.z;
                acc[i][3] += wv * xv.w;
            }
        }
        __syncthreads();
    }
    float* outb = out + ((size_t)b * Mtot + m0) * HW_ + hw0;
#pragma unroll
    for (int i = 0; i < 4; i++) {
        float4 v = make_float4(acc[i][0], acc[i][1], acc[i][2], acc[i][3]);
        *reinterpret_cast<float4*>(outb + (size_t)(ty + 16 * i) * HW_ + tx * 4) = v;
    }

    // fused per-channel partial (sum, sumsq) over this block's 64 pixels
#pragma unroll
    for (int i = 0; i < 4; i++) {
        float s = acc[i][0] + acc[i][1] + acc[i][2] + acc[i][3];
        float q = acc[i][0] * acc[i][0] + acc[i][1] * acc[i][1]
                + acc[i][2] * acc[i][2] + acc[i][3] * acc[i][3];
#pragma unroll
        for (int off = 8; off > 0; off >>= 1) {
            s += __shfl_down_sync(0xffffffffu, s, off, 16);
            q += __shfl_down_sync(0xffffffffu, q, off, 16);
        }
        if (tx == 0) {
            int ch = m0 + ty + 16 * i;
            ps[(size_t)ch * NB_GEMM + bx] = s;
            pq[(size_t)ch * NB_GEMM + bx] = q;
        }
    }
}

// ---------------- reduce conv (M=16, K=64) + fused partial stats -----------------
__global__ void __launch_bounds__(256)
conv_wr_kernel(const float* __restrict__ in, const float* __restrict__ wr,
               const float* __restrict__ scale, const float* __restrict__ shift,
               float* __restrict__ out, float* __restrict__ ps, float* __restrict__ pq)
{
    __shared__ float swT[64][16];   // transposed weights [c][m]
    __shared__ float ssc[64], ssh[64];
    const int tid = threadIdx.x;
    for (int e = tid; e < 16 * 64; e += 256) { int m = e >> 6, c = e & 63; swT[c][m] = wr[e]; }
    if (tid < 64) { ssc[tid] = scale[tid]; ssh[tid] = shift[tid]; }
    __syncthreads();

    const int p  = blockIdx.x * 256 + tid;
    const int b  = p / HW_, hw = p % HW_;
    const float* pin = in + (size_t)b * MID * HW_ + hw;

    float acc[16];
#pragma unroll
    for (int m = 0; m < 16; m++) acc[m] = 0.f;

#pragma unroll 4
    for (int c = 0; c < 64; c++) {
        float v = fmaxf(pin[(size_t)c * HW_] * ssc[c] + ssh[c], 0.f);
        const float4* w4 = reinterpret_cast<const float4*>(swT[c]);
#pragma unroll
        for (int q = 0; q < 4; q++) {
            float4 w = w4[q];
            acc[4 * q + 0] += w.x * v;
            acc[4 * q + 1] += w.y * v;
            acc[4 * q + 2] += w.z * v;
            acc[4 * q + 3] += w.w * v;
        }
    }
    float* pout = out + (size_t)b * RED * HW_ + hw;
#pragma unroll
    for (int m = 0; m < 16; m++) pout[(size_t)m * HW_] = acc[m];

    const int wid = tid >> 5, lane = tid & 31;
    __shared__ float wsum[8][16], wq[8][16];
#pragma unroll
    for (int m = 0; m < 16; m++) {
        float s = acc[m], q = acc[m] * acc[m];
#pragma unroll
        for (int off = 16; off > 0; off >>= 1) {
            s += __shfl_down_sync(0xffffffffu, s, off);
            q += __shfl_down_sync(0xffffffffu, q, off);
        }
        if (lane == 0) { wsum[wid][m] = s; wq[wid][m] = q; }
    }
    __syncthreads();
    if (tid < 16) {
        float s = 0.f, q = 0.f;
#pragma unroll
        for (int w = 0; w < 8; w++) { s += wsum[w][tid]; q += wq[w][tid]; }
        ps[tid * NB_WR + blockIdx.x] = s;
        pq[tid * NB_WR + blockIdx.x] = q;
    }
}

// ---------------- fused involution v4: dy-row grouping, ILP-split wk dots --------
// grid (14 row-tiles, 4 groups, 8 batch), block 224 (= 4 rows x 56 cols).
// z tile pixel-major pad-20 (4x LDS.128 per tap). Per dy-row: 7 wk dots computed
// as 28 independent 4-FMA chains (latency ~18 cyc vs 64 serial), then 7 MAC bursts.
__global__ void __launch_bounds__(224, 3)
involution_kernel(const float* __restrict__ buf1, const float* __restrict__ tin,
                  const float* __restrict__ ws,
                  const float* __restrict__ pst, const float* __restrict__ pqt,
                  const float* __restrict__ gr, const float* __restrict__ br,
                  const float* __restrict__ scale, const float* __restrict__ shift,
                  float* __restrict__ out, float* __restrict__ ps, float* __restrict__ pq)
{
    extern __shared__ float smem[];
    float* s_z  = smem;                     // [620][20] = 12400 (pixel-major, pad 20)
    float* s_t  = smem + 12400;             // [16][224] = 3584 (raw t tile)
    float* s_sw = smem + 12400 + 3584;      // [49][16]  = 784
    float* s_tc = smem + 12400 + 3584 + 784;// [16]
    float* s_th = s_tc + 16;                // [16]

    const int rt = blockIdx.x, g = blockIdx.y, b = blockIdx.z;
    const int r0 = rt * 4;
    const int tid = threadIdx.x;

    // ws rows for this group: [49][16]
    for (int e = tid; e < KK * RED; e += 224) s_sw[e] = ws[(size_t)g * KK * RED + e];

    // fused BNt finalize: 16 channels, 8 lanes each (threads 0..127)
    if (tid < 128) {
        int ch = tid >> 3, part = tid & 7;
        float s = 0.f, q = 0.f;
        for (int i = part; i < NB_WR; i += 8) {
            s += pst[ch * NB_WR + i];
            q += pqt[ch * NB_WR + i];
        }
#pragma unroll
        for (int off = 4; off > 0; off >>= 1) {
            s += __shfl_down_sync(0xffffffffu, s, off, 8);
            q += __shfl_down_sync(0xffffffffu, q, off, 8);
        }
        if (part == 0) {
            const float nn = (float)NPIX;
            float m = s / nn;
            float v = q / nn - m * m;
            float sc = gr[ch] * rsqrtf(v + 1e-5f);
            s_tc[ch] = sc;
            s_th[ch] = br[ch] - m * sc;
        }
    }

    // raw t tile: [16][224]
    {
        const float* src = tin + (size_t)b * RED * HW_ + r0 * 56;
#pragma unroll
        for (int c = 0; c < 16; c++)
            s_t[c * 224 + tid] = src[(size_t)c * HW_ + tid];
    }

    // z1 tile with halo, BN1 affine + ReLU on load; PIXEL-MAJOR pad-20 layout.
    {
        const float* src = buf1 + ((size_t)b * MID + g * GC_) * HW_;
        for (int e = tid; e < 16 * 620; e += 224) {
            int c   = e / 620;
            int p   = e - c * 620;
            int ry  = p / 62;
            int cx  = p - ry * 62;
            int gy  = r0 - 3 + ry;
            int gx  = cx - 3;
            float v = 0.f;
            if (gy >= 0 && gy < 56 && gx >= 0 && gx < 56) {
                int ch = g * GC_ + c;
                v = fmaxf(src[(size_t)c * HW_ + gy * 56 + gx] * scale[ch] + shift[ch], 0.f);
            }
            s_z[p * 20 + c] = v;
        }
    }
    __syncthreads();

    // per-thread t vector with BNt affine + ReLU
    float t[16];
#pragma unroll
    for (int c = 0; c < 16; c++)
        t[c] = fmaxf(s_t[c * 224 + tid] * s_tc[c] + s_th[c], 0.f);

    const int row = tid / 56, col = tid % 56;
    float acc[16];
#pragma unroll
    for (int c = 0; c < 16; c++) acc[c] = 0.f;

    for (int dy = 0; dy < 7; dy++) {
        // 7 per-pixel kernel values for this dy-row: 28 independent 4-FMA chains
        float wk[7];
#pragma unroll
        for (int dx = 0; dx < 7; dx++) {
            const float4* w4 = reinterpret_cast<const float4*>(&s_sw[(dy * 7 + dx) * 16]);
            float4 wa = w4[0], wb = w4[1], wc = w4[2], wd = w4[3];
            float d0 = wa.x * t[0]  + wa.y * t[1]  + wa.z * t[2]  + wa.w * t[3];
            float d1 = wb.x * t[4]  + wb.y * t[5]  + wb.z * t[6]  + wb.w * t[7];
            float d2 = wc.x * t[8]  + wc.y * t[9]  + wc.z * t[10] + wc.w * t[11];
            float d3 = wd.x * t[12] + wd.y * t[13] + wd.z * t[14] + wd.w * t[15];
            wk[dx] = (d0 + d1) + (d2 + d3);
        }
        const float* zbase = s_z + ((row + dy) * 62 + col) * 20;
#pragma unroll
        for (int dx = 0; dx < 7; dx++) {
            const float4* zp = reinterpret_cast<const float4*>(zbase + dx * 20);
            float4 z0 = zp[0], z1 = zp[1], z2 = zp[2], z3 = zp[3];
            float w = wk[dx];
            acc[0]  += w * z0.x;  acc[1]  += w * z0.y;  acc[2]  += w * z0.z;  acc[3]  += w * z0.w;
            acc[4]  += w * z1.x;  acc[5]  += w * z1.y;  acc[6]  += w * z1.z;  acc[7]  += w * z1.w;
            acc[8]  += w * z2.x;  acc[9]  += w * z2.y;  acc[10] += w * z2.z;  acc[11] += w * z2.w;
            acc[12] += w * z3.x;  acc[13] += w * z3.y;  acc[14] += w * z3.z;  acc[15] += w * z3.w;
        }
    }

    float* dst = out + ((size_t)b * MID + g * GC_) * HW_ + r0 * 56 + tid;
#pragma unroll
    for (int c = 0; c < 16; c++) dst[(size_t)c * HW_] = acc[c];

    // fused BN2 partial stats (7 warps)
    const int wid = tid >> 5, lane = tid & 31;
    __shared__ float wsum[7][16], wq[7][16];
#pragma unroll
    for (int c = 0; c < 16; c++) {
        float s = acc[c], q = acc[c] * acc[c];
#pragma unroll
        for (int off = 16; off > 0; off >>= 1) {
            s += __shfl_down_sync(0xffffffffu, s, off);
            q += __shfl_down_sync(0xffffffffu, q, off);
        }
        if (lane == 0) { wsum[wid][c] = s; wq[wid][c] = q; }
    }
    __syncthreads();
    if (tid < 16) {
        float s = 0.f, q = 0.f;
#pragma unroll
        for (int w = 0; w < 7; w++) { s += wsum[w][tid]; q += wq[w][tid]; }
        int ch = g * GC_ + tid;
        int slot = b * 14 + rt;
        ps[(size_t)ch * NB_INV + slot] = s;
        pq[(size_t)ch * NB_INV + slot] = q;
    }
}

// ---------------- epilogue: relu(bn(y3) + x), fused BN3 finalize ------------------
__global__ void __launch_bounds__(256)
final_kernel(const float4* __restrict__ y3, const float4* __restrict__ xin,
             const float* __restrict__ ps, const float* __restrict__ pq,
             const float* __restrict__ g3, const float* __restrict__ b3,
             float4* __restrict__ out)
{
    const int bc = blockIdx.x;          // b*256 + c
    const int c  = bc & 255;
    const int tid = threadIdx.x;

    __shared__ float sh_s[256], sh_q[256];
    __shared__ float s_sc, s_sh;
    {
        float s = 0.f, q = 0.f;
        for (int i = tid; i < NB_GEMM; i += 256) {
            s += ps[(size_t)c * NB_GEMM + i];
            q += pq[(size_t)c * NB_GEMM + i];
        }
        sh_s[tid] = s; sh_q[tid] = q;
        __syncthreads();
        for (int off = 128; off > 0; off >>= 1) {
            if (tid < off) { sh_s[tid] += sh_s[tid + off]; sh_q[tid] += sh_q[tid + off]; }
            __syncthreads();
        }
        if (tid == 0) {
            const float nn = (float)NPIX;
            float m = sh_s[0] / nn;
            float v = sh_q[0] / nn - m * m;
            float sc = g3[c] * rsqrtf(v + 1e-5f);
            s_sc = sc;
            s_sh = b3[c] - m * sc;
        }
        __syncthreads();
    }
    const float s = s_sc, sh = s_sh;
    const size_t base = (size_t)bc * 784;      // 784 float4 per (b,c)
    for (int j = tid; j < 784; j += 256) {
        float4 a = y3[base + j], r0 = xin[base + j], r;
        r.x = fmaxf(a.x * s + sh + r0.x, 0.f);
        r.y = fmaxf(a.y * s + sh + r0.y, 0.f);
        r.z = fmaxf(a.z * s + sh + r0.z, 0.f);
        r.w = fmaxf(a.w * s + sh + r0.w, 0.f);
        out[base + j] = r;
    }
}

// ---------------- launch ---------------------------------------------------------
static void* sym_addr(const void* s) { void* p = nullptr; cudaGetSymbolAddress(&p, s); return p; }

extern "C" void kernel_launch(void* const* d_in, const int* in_sizes, int n_in,
                              void* d_out, int out_size)
{
    const float* x  = (const float*)d_in[0];
    const float* w1 = (const float*)d_in[1];
    const float* g1 = (const float*)d_in[2];
    const float* b1 = (const float*)d_in[3];
    const float* wr = (const float*)d_in[4];
    const float* gr = (const float*)d_in[5];
    const float* br = (const float*)d_in[6];
    const float* ws = (const float*)d_in[7];
    const float* g2 = (const float*)d_in[8];
    const float* b2 = (const float*)d_in[9];
    const float* w3 = (const float*)d_in[10];
    const float* g3 = (const float*)d_in[11];
    const float* b3 = (const float*)d_in[12];
    float* out = (float*)d_out;

    float* buf1 = (float*)sym_addr(g_buf1);
    float* tbuf = (float*)sym_addr(g_t);
    float* invb = (float*)sym_addr(g_inv);
    float* y3   = (float*)sym_addr(g_y3);
    float* ps1 = (float*)sym_addr(g_ps1);  float* pq1 = (float*)sym_addr(g_pq1);
    float* pst = (float*)sym_addr(g_pst);  float* pqt = (float*)sym_addr(g_pqt);
    float* ps2 = (float*)sym_addr(g_ps2);  float* pq2 = (float*)sym_addr(g_pq2);
    float* ps3 = (float*)sym_addr(g_ps3);  float* pq3 = (float*)sym_addr(g_pq3);
    float* sc1 = (float*)sym_addr(g_sc1);  float* sh1 = (float*)sym_addr(g_sh1);
    float* sc2 = (float*)sym_addr(g_sc2);  float* sh2 = (float*)sym_addr(g_sh2);

    // smem: 12400 (z pad-20) + 3584 (t) + 784 (ws) + 32 (bn_t) floats = 67200 bytes
    const int inv_smem = (12400 + 3584 + 784 + 32) * 4;
    cudaFuncSetAttribute(involution_kernel, cudaFuncAttributeMaxDynamicSharedMemorySize, inv_smem);

    // 1) conv1: [8,256,HW] -> buf1 [8,64,HW] (+BN1 partials)
    gemm64_kernel<256, false><<<dim3(NB_GEMM, 1), 256>>>(x, w1, buf1, MID, nullptr, nullptr, ps1, pq1);
    // 2) BN1 finalize (dual consumer: conv_wr + involution)
    finalize_kernel<<<MID, 256>>>(ps1, pq1, NB_GEMM, g1, b1, sc1, sh1);
    // 3) reduce conv: relu(bn(buf1)) -> t (+BNt partials)
    conv_wr_kernel<<<NB_WR, 256>>>(buf1, wr, sc1, sh1, tbuf, pst, pqt);
    // 4) fused involution v4 (ILP-split wk dots) -> inv (+BN2 partials)
    involution_kernel<<<dim3(14, GRP, B_), 224, inv_smem>>>(buf1, tbuf, ws, pst, pqt, gr, br,
                                                            sc1, sh1, invb, ps2, pq2);
    // 5) BN2 finalize
    finalize_kernel<<<MID, 256>>>(ps2, pq2, NB_INV, g2, b2, sc2, sh2);
    // 6) conv3: relu(bn(inv)) -> y3 [8,256,HW] (+BN3 partials)
    gemm64_kernel<64, true><<<dim3(NB_GEMM, 4), 256>>>(invb, w3, y3, C1, sc2, sh2, ps3, pq3);
    // 7) epilogue (fused BN3 finalize): relu(bn(y3) + x)
    final_kernel<<<B_ * C1, 256>>>((const float4*)y3, (const float4*)x, ps3, pq3, g3, b3, (float4*)out);
}